// round 3
// baseline (speedup 1.0000x reference)
#include <cuda_runtime.h>
#include <math.h>

#define DIMV 1920
#define T_TXT 226
#define SVID 2048
#define SEQ 2274
#define NH 30
#define HD 64

// ---------------- scratch (device globals; no allocation allowed) ----------------
__device__ float g_hs[SEQ * DIMV];        // concat(encoder, hidden)
__device__ float g_q[NH * SEQ * HD];      // head-major
__device__ float g_k[NH * SEQ * HD];
__device__ float g_v[NH * SEQ * HD];
__device__ float g_attn[SEQ * DIMV];      // attention output [s][dim] (+conv branch)
__device__ float g_gelu[256 * 128 * 8];   // conv1+gelu intermediate [p][r][f]

// ---------------- generic NT GEMM: C = A(MxK) @ B(NxK)^T + bias ----------------
// MODE 0: write to head-major qkv layout  dst[((n>>6)*SEQ + m)*64 + (n&63)]
// MODE 1: write with row remap (video rows first, then text) dst[remap(m)*N + n]
template <int MODE>
__global__ void __launch_bounds__(256) gemm_nt(
    const float* __restrict__ A, const float* __restrict__ B,
    const float* __restrict__ bias, float* __restrict__ C,
    int M, int N, int K, long long out_limit)
{
    __shared__ __align__(16) float As[16][128];
    __shared__ __align__(16) float Bs[16][128];
    int tid = threadIdx.x;
    int tx = tid & 15, ty = tid >> 4;
    int m0 = blockIdx.x * 128, n0 = blockIdx.y * 128;
    float acc[8][8] = {};

    for (int k0 = 0; k0 < K; k0 += 16) {
#pragma unroll
        for (int i = 0; i < 8; i++) {
            int idx = tid + i * 256;
            int kk = idx & 15, mm = idx >> 4;
            float a = (m0 + mm < M) ? A[(m0 + mm) * K + k0 + kk] : 0.f;
            As[kk][mm] = a;
            float b = (n0 + mm < N) ? B[(n0 + mm) * K + k0 + kk] : 0.f;
            Bs[kk][mm] = b;
        }
        __syncthreads();
#pragma unroll
        for (int kk = 0; kk < 16; kk++) {
            float a[8], b[8];
            float4 a0 = *(const float4*)&As[kk][ty * 8];
            float4 a1 = *(const float4*)&As[kk][ty * 8 + 4];
            float4 b0 = *(const float4*)&Bs[kk][tx * 8];
            float4 b1 = *(const float4*)&Bs[kk][tx * 8 + 4];
            a[0] = a0.x; a[1] = a0.y; a[2] = a0.z; a[3] = a0.w;
            a[4] = a1.x; a[5] = a1.y; a[6] = a1.z; a[7] = a1.w;
            b[0] = b0.x; b[1] = b0.y; b[2] = b0.z; b[3] = b0.w;
            b[4] = b1.x; b[5] = b1.y; b[6] = b1.z; b[7] = b1.w;
#pragma unroll
            for (int i = 0; i < 8; i++)
#pragma unroll
                for (int j = 0; j < 8; j++) acc[i][j] += a[i] * b[j];
        }
        __syncthreads();
    }

#pragma unroll
    for (int i = 0; i < 8; i++) {
        int m = m0 + ty * 8 + i;
        if (m >= M) continue;
#pragma unroll
        for (int j = 0; j < 8; j++) {
            int n = n0 + tx * 8 + j;
            if (n >= N) continue;
            float val = acc[i][j] + bias[n];
            if (MODE == 0) {
                C[((n >> 6) * SEQ + m) * 64 + (n & 63)] = val;
            } else {
                int r = (m >= T_TXT) ? (m - T_TXT) : (SVID + m);
                long long idx = (long long)r * N + n;
                if (idx < out_limit) C[idx] = val;
            }
        }
    }
}

// ---------------- per-(head,pos) LayerNorm(HD=64) + RoPE on video rows ----------------
__global__ void __launch_bounds__(128) ln_rope_kernel(
    float* __restrict__ qbuf, float* __restrict__ kbuf,
    const float* __restrict__ cosb, const float* __restrict__ sinb,
    const float* __restrict__ nqw, const float* __restrict__ nqb,
    const float* __restrict__ nkw, const float* __restrict__ nkb)
{
    int warp = threadIdx.x >> 5, lane = threadIdx.x & 31;
    int row = blockIdx.x * 4 + warp;
    const int ROWS = NH * SEQ;
    if (row >= 2 * ROWS) return;
    int zk = (row >= ROWS) ? 1 : 0;
    int rem = zk ? (row - ROWS) : row;
    int s = rem % SEQ;
    float* x = (zk ? kbuf : qbuf) + rem * HD;
    const float* wgt = zk ? nkw : nqw;
    const float* bia = zk ? nkb : nqb;

    float v0 = x[2 * lane], v1 = x[2 * lane + 1];
    float sum = v0 + v1;
#pragma unroll
    for (int o = 16; o; o >>= 1) sum += __shfl_xor_sync(0xffffffffu, sum, o);
    float mu = sum * (1.f / 64.f);
    float d0 = v0 - mu, d1 = v1 - mu;
    float vs = d0 * d0 + d1 * d1;
#pragma unroll
    for (int o = 16; o; o >>= 1) vs += __shfl_xor_sync(0xffffffffu, vs, o);
    float rstd = rsqrtf(vs * (1.f / 64.f) + 1e-6f);
    float y0 = d0 * rstd * wgt[2 * lane] + bia[2 * lane];
    float y1 = d1 * rstd * wgt[2 * lane + 1] + bia[2 * lane + 1];
    if (s >= T_TXT) {
        int sv = s - T_TXT;
        float c0 = cosb[sv * HD + 2 * lane], c1 = cosb[sv * HD + 2 * lane + 1];
        float sn0 = sinb[sv * HD + 2 * lane], sn1 = sinb[sv * HD + 2 * lane + 1];
        float r0v = y0 * c0 - y1 * sn0;   // x_rot[2i]   = -x[2i+1]
        float r1v = y1 * c1 + y0 * sn1;   // x_rot[2i+1] =  x[2i]
        y0 = r0v; y1 = r1v;
    }
    x[2 * lane] = y0;
    x[2 * lane + 1] = y1;
}

// ---------------- flash attention, fp32, BQ=64 BKV=32 ----------------
__global__ void __launch_bounds__(256) attention_kernel(
    const float* __restrict__ q, const float* __restrict__ k,
    const float* __restrict__ v, float* __restrict__ attn)
{
    __shared__ __align__(16) float Qs[64][65];
    __shared__ __align__(16) float Ks[32][65];
    __shared__ __align__(16) float Vs[32][68];
    __shared__ __align__(16) float Ps[64][36];
    __shared__ float ms[64], ls[64], cs[64];

    int tid = threadIdx.x;
    int h = blockIdx.y;
    int q0 = blockIdx.x * 64;
    const float* qh = q + (h * SEQ) * HD;
    const float* kh = k + (h * SEQ) * HD;
    const float* vh = v + (h * SEQ) * HD;

#pragma unroll
    for (int i = 0; i < 16; i++) {
        int idx = tid + i * 256;
        int r = idx >> 6, d = idx & 63;
        Qs[r][d] = (q0 + r < SEQ) ? qh[(q0 + r) * HD + d] : 0.f;
    }
    if (tid < 64) { ms[tid] = -1e30f; ls[tid] = 0.f; }
    float O[4][4] = {};
    __syncthreads();

    int tr = tid >> 3, tc = tid & 7;
    int r0 = tr * 2, c0 = tc * 4;
    int ty = tid >> 4, tx = tid & 15;

    for (int kv0 = 0; kv0 < SEQ; kv0 += 32) {
        int jmax = min(32, SEQ - kv0);
        // load K/V tile
#pragma unroll
        for (int i = 0; i < 8; i++) {
            int idx = tid + i * 256;
            int r = idx >> 6, d = idx & 63;
            float kk = (r < jmax) ? kh[(kv0 + r) * HD + d] : 0.f;
            float vv = (r < jmax) ? vh[(kv0 + r) * HD + d] : 0.f;
            Ks[r][d] = kk;
            Vs[r][d] = vv;
        }
        __syncthreads();

        // scores: 2 q-rows x 4 k-cols per thread
        float s0[4] = {}, s1[4] = {};
#pragma unroll
        for (int d = 0; d < 64; d++) {
            float qa = Qs[r0][d], qb = Qs[r0 + 1][d];
            float k0v = Ks[c0][d], k1v = Ks[c0 + 1][d];
            float k2v = Ks[c0 + 2][d], k3v = Ks[c0 + 3][d];
            s0[0] += qa * k0v; s0[1] += qa * k1v; s0[2] += qa * k2v; s0[3] += qa * k3v;
            s1[0] += qb * k0v; s1[1] += qb * k1v; s1[2] += qb * k2v; s1[3] += qb * k3v;
        }
#pragma unroll
        for (int j = 0; j < 4; j++) {
            Ps[r0][c0 + j] = s0[j] * 0.125f;
            Ps[r0 + 1][c0 + j] = s1[j] * 0.125f;
        }
        __syncthreads();

        // online softmax stats (one thread per q-row)
        if (tid < 64) {
            float mo = ms[tid], mx = mo;
            for (int j = 0; j < jmax; j++) mx = fmaxf(mx, Ps[tid][j]);
            float c = __expf(mo - mx);
            float sum = 0.f;
            for (int j = 0; j < jmax; j++) {
                float p = __expf(Ps[tid][j] - mx);
                Ps[tid][j] = p;
                sum += p;
            }
            for (int j = jmax; j < 32; j++) Ps[tid][j] = 0.f;
            ls[tid] = ls[tid] * c + sum;
            ms[tid] = mx;
            cs[tid] = c;
        }
        __syncthreads();

        // O = O*c + P @ V   (4 q-rows x 4 d-cols per thread)
        float cc[4];
#pragma unroll
        for (int ii = 0; ii < 4; ii++) cc[ii] = cs[ty * 4 + ii];
#pragma unroll
        for (int ii = 0; ii < 4; ii++)
#pragma unroll
            for (int jj = 0; jj < 4; jj++) O[ii][jj] *= cc[ii];
#pragma unroll 4
        for (int j = 0; j < 32; j++) {
            float4 vv = *(const float4*)&Vs[j][tx * 4];
            float p0 = Ps[ty * 4 + 0][j];
            float p1 = Ps[ty * 4 + 1][j];
            float p2 = Ps[ty * 4 + 2][j];
            float p3 = Ps[ty * 4 + 3][j];
            O[0][0] += p0 * vv.x; O[0][1] += p0 * vv.y; O[0][2] += p0 * vv.z; O[0][3] += p0 * vv.w;
            O[1][0] += p1 * vv.x; O[1][1] += p1 * vv.y; O[1][2] += p1 * vv.z; O[1][3] += p1 * vv.w;
            O[2][0] += p2 * vv.x; O[2][1] += p2 * vv.y; O[2][2] += p2 * vv.z; O[2][3] += p2 * vv.w;
            O[3][0] += p3 * vv.x; O[3][1] += p3 * vv.y; O[3][2] += p3 * vv.z; O[3][3] += p3 * vv.w;
        }
        __syncthreads();
    }

#pragma unroll
    for (int ii = 0; ii < 4; ii++) {
        int s = q0 + ty * 4 + ii;
        if (s < SEQ) {
            float inv = 1.f / ls[ty * 4 + ii];
#pragma unroll
            for (int jj = 0; jj < 4; jj++)
                attn[s * DIMV + h * HD + tx * 4 + jj] = O[ii][jj] * inv;
        }
    }
}

// ---------------- conv1 (DIM->RANK, k=3, pad 1 over F=8) + exact GELU ----------------
__global__ void __launch_bounds__(128) conv1_gelu_kernel(
    const float* __restrict__ hidden, const float* __restrict__ w1,
    float* __restrict__ gel)
{
    __shared__ float xs[256][9];
    int p = blockIdx.x;       // spatial position 0..255
    int r = threadIdx.x;      // rank channel 0..127
    float acc[8] = {};
    for (int d0 = 0; d0 < DIMV; d0 += 256) {
        int dmax = min(256, DIMV - d0);   // FIX: DIMV=1920 is not a multiple of 256
        for (int i = threadIdx.x; i < 2048; i += 128) {
            int d = i & 255, f = i >> 8;
            xs[d][f] = (d < dmax) ? hidden[(f * 256 + p) * DIMV + d0 + d] : 0.f;
        }
        __syncthreads();
#pragma unroll 2
        for (int d = 0; d < dmax; d++) {
            const float* w = w1 + r * (DIMV * 3) + (d0 + d) * 3;
            float w0 = w[0], wm = w[1], w2 = w[2];
            float xp[10];
            xp[0] = 0.f; xp[9] = 0.f;
#pragma unroll
            for (int f = 0; f < 8; f++) xp[f + 1] = xs[d][f];
#pragma unroll
            for (int f = 0; f < 8; f++)
                acc[f] += w0 * xp[f] + wm * xp[f + 1] + w2 * xp[f + 2];
        }
        __syncthreads();
    }
#pragma unroll
    for (int f = 0; f < 8; f++) {
        float x = acc[f];
        float g = 0.5f * x * (1.f + erff(x * 0.70710678118654752f));
        gel[(p * 128 + r) * 8 + f] = g;
    }
}

// ---------------- conv2 (RANK->DIM, k=3, pad 1) fused add into attn buffer ----------------
__global__ void __launch_bounds__(256) conv2_add_kernel(
    const float* __restrict__ w2, const float* __restrict__ gel,
    float* __restrict__ attn)
{
    __shared__ float gs[128][10];
    int p = blockIdx.x;
    int tid = threadIdx.x;
    for (int i = tid; i < 1024; i += 256) {
        int rr = i >> 3, f = i & 7;
        gs[rr][f + 1] = gel[(p * 128 + rr) * 8 + f];
    }
    if (tid < 128) { gs[tid][0] = 0.f; gs[tid][9] = 0.f; }
    __syncthreads();

    for (int d = tid; d < DIMV; d += 256) {
        float acc[8] = {};
        const float* w = w2 + d * 384;
#pragma unroll 2
        for (int rr = 0; rr < 128; rr++) {
            float w0 = w[rr * 3], wm = w[rr * 3 + 1], w2v = w[rr * 3 + 2];
#pragma unroll
            for (int f = 0; f < 8; f++)
                acc[f] += w0 * gs[rr][f] + wm * gs[rr][f + 1] + w2v * gs[rr][f + 2];
        }
#pragma unroll
        for (int f = 0; f < 8; f++) {
            int s = T_TXT + f * 256 + p;
            attn[s * DIMV + d] += acc[f];
        }
    }
}

// ---------------- launch ----------------
extern "C" void kernel_launch(void* const* d_in, const int* in_sizes, int n_in,
                              void* d_out, int out_size)
{
    const float* hidden = (const float*)d_in[0];
    const float* enc    = (const float*)d_in[1];
    const float* cosb   = (const float*)d_in[2];
    const float* sinb   = (const float*)d_in[3];
    const float* qw = (const float*)d_in[4];
    const float* qb = (const float*)d_in[5];
    const float* kw = (const float*)d_in[6];
    const float* kb = (const float*)d_in[7];
    const float* vw = (const float*)d_in[8];
    const float* vb = (const float*)d_in[9];
    const float* nqw = (const float*)d_in[10];
    const float* nqb = (const float*)d_in[11];
    const float* nkw = (const float*)d_in[12];
    const float* nkb = (const float*)d_in[13];
    const float* w1 = (const float*)d_in[14];
    const float* w2 = (const float*)d_in[15];
    const float* ow = (const float*)d_in[16];
    const float* ob = (const float*)d_in[17];

    float *hs, *q, *k, *v, *attn, *gel;
    cudaGetSymbolAddress((void**)&hs,   g_hs);
    cudaGetSymbolAddress((void**)&q,    g_q);
    cudaGetSymbolAddress((void**)&k,    g_k);
    cudaGetSymbolAddress((void**)&v,    g_v);
    cudaGetSymbolAddress((void**)&attn, g_attn);
    cudaGetSymbolAddress((void**)&gel,  g_gelu);

    // hs = concat([encoder, hidden]) along sequence
    cudaMemcpyAsync(hs, enc, (size_t)T_TXT * DIMV * sizeof(float),
                    cudaMemcpyDeviceToDevice, 0);
    cudaMemcpyAsync(hs + T_TXT * DIMV, hidden, (size_t)SVID * DIMV * sizeof(float),
                    cudaMemcpyDeviceToDevice, 0);

    dim3 gg((SEQ + 127) / 128, DIMV / 128);   // 18 x 15
    gemm_nt<0><<<gg, 256>>>(hs, qw, qb, q, SEQ, DIMV, DIMV, 0);
    gemm_nt<0><<<gg, 256>>>(hs, kw, kb, k, SEQ, DIMV, DIMV, 0);
    gemm_nt<0><<<gg, 256>>>(hs, vw, vb, v, SEQ, DIMV, DIMV, 0);

    ln_rope_kernel<<<(2 * NH * SEQ + 3) / 4, 128>>>(q, k, cosb, sinb, nqw, nqb, nkw, nkb);

    attention_kernel<<<dim3((SEQ + 63) / 64, NH), 256>>>(q, k, v, attn);

    conv1_gelu_kernel<<<256, 128>>>(hidden, w1, gel);
    conv2_add_kernel<<<256, 256>>>(w2, gel, attn);

    gemm_nt<1><<<gg, 256>>>(attn, ow, ob, (float*)d_out, SEQ, DIMV, DIMV,
                            (long long)out_size);
}

// round 5
// speedup vs baseline: 1.2906x; 1.2906x over previous
#include <cuda_runtime.h>
#include <math.h>
#include <stdint.h>

#define DIMV 1920
#define T_TXT 226
#define SVID 2048
#define SEQ 2274
#define NH 30
#define HD 64

// ---------------- scratch (device globals; no allocation allowed) ----------------
__device__ float g_hs[SEQ * DIMV];        // concat(encoder, hidden)
__device__ float g_q[NH * SEQ * HD];      // head-major
__device__ float g_k[NH * SEQ * HD];
__device__ float g_v[NH * SEQ * HD];
__device__ float g_attn[SEQ * DIMV];      // attention output [s][dim] (+conv branch)
__device__ float g_gelu[256 * 128 * 8];   // conv1+gelu intermediate [p][r][f]

// ---------------- tf32 helpers ----------------
__device__ __forceinline__ uint32_t f2tf32(float x) {
    uint32_t r;
    asm("cvt.rna.tf32.f32 %0, %1;" : "=r"(r) : "f"(x));
    return r;
}
__device__ __forceinline__ void split_tf32(float x, uint32_t& hi, uint32_t& lo) {
    hi = f2tf32(x);
    lo = f2tf32(x - __uint_as_float(hi));
}
__device__ __forceinline__ void mma_tf32(float* d, const uint32_t* a, const uint32_t* b) {
    asm volatile(
        "mma.sync.aligned.m16n8k8.row.col.f32.tf32.tf32.f32 "
        "{%0,%1,%2,%3}, {%4,%5,%6,%7}, {%8,%9}, {%0,%1,%2,%3};"
        : "+f"(d[0]), "+f"(d[1]), "+f"(d[2]), "+f"(d[3])
        : "r"(a[0]), "r"(a[1]), "r"(a[2]), "r"(a[3]), "r"(b[0]), "r"(b[1]));
}

// ---------------- 3xTF32 tensor-core NT GEMM: C = A(MxK) @ B(NxK)^T + bias ----------------
// MODE 0: write to head-major qkv layout  dst[((n>>6)*SEQ + m)*64 + (n&63)]
// MODE 1: write with row remap (video rows first, then text) dst[remap(m)*N + n]
// Requires K % 32 == 0, N % 128 == 0 (holds: K=N=1920).
template <int MODE>
__global__ void __launch_bounds__(256) gemm_tf32(
    const float* __restrict__ A, const float* __restrict__ B,
    const float* __restrict__ bias, float* __restrict__ C,
    int M, int N, int K, long long out_limit)
{
    __shared__ __align__(16) float As[128][36];   // [m][k], pad 4 -> conflict-free
    __shared__ __align__(16) float Bs[128][36];   // [n][k]

    int tid  = threadIdx.x;
    int lane = tid & 31;
    int warp = tid >> 5;
    int wm = (warp >> 1) * 32;   // warp row offset within block tile (4 warps)
    int wn = (warp & 1) * 64;    // warp col offset within block tile (2 warps)
    int gr = lane >> 2;          // fragment group row (0..7)
    int gc = lane & 3;           // fragment group col (0..3)

    int m0 = blockIdx.x * 128, n0 = blockIdx.y * 128;

    float acc[2][8][4];
#pragma unroll
    for (int i = 0; i < 2; i++)
#pragma unroll
        for (int j = 0; j < 8; j++)
#pragma unroll
            for (int t = 0; t < 4; t++) acc[i][j][t] = 0.f;

    for (int k0 = 0; k0 < K; k0 += 32) {
        // fill smem: 128 rows x 8 float4 per tile, 4 float4 per thread per tile
#pragma unroll
        for (int i = 0; i < 4; i++) {
            int idx = tid + i * 256;
            int row = idx >> 3, c4 = idx & 7;
            float4 av = make_float4(0.f, 0.f, 0.f, 0.f);
            if (m0 + row < M)
                av = *(const float4*)&A[(size_t)(m0 + row) * K + k0 + c4 * 4];
            *(float4*)&As[row][c4 * 4] = av;
            float4 bv = *(const float4*)&B[(size_t)(n0 + row) * K + k0 + c4 * 4];
            *(float4*)&Bs[row][c4 * 4] = bv;
        }
        __syncthreads();

#pragma unroll
        for (int kk = 0; kk < 4; kk++) {
            int kb = kk * 8;
            // A fragments (2 m-frags x 4 regs), split hi/lo
            uint32_t a_hi[2][4], a_lo[2][4];
#pragma unroll
            for (int mf = 0; mf < 2; mf++) {
                int r = wm + mf * 16 + gr;
                split_tf32(As[r][kb + gc],         a_hi[mf][0], a_lo[mf][0]);
                split_tf32(As[r + 8][kb + gc],     a_hi[mf][1], a_lo[mf][1]);
                split_tf32(As[r][kb + gc + 4],     a_hi[mf][2], a_lo[mf][2]);
                split_tf32(As[r + 8][kb + gc + 4], a_hi[mf][3], a_lo[mf][3]);
            }
            // B fragments (8 n-frags x 2 regs), split hi/lo
            uint32_t b_hi[8][2], b_lo[8][2];
#pragma unroll
            for (int nf = 0; nf < 8; nf++) {
                int c = wn + nf * 8 + gr;
                split_tf32(Bs[c][kb + gc],     b_hi[nf][0], b_lo[nf][0]);
                split_tf32(Bs[c][kb + gc + 4], b_hi[nf][1], b_lo[nf][1]);
            }
#pragma unroll
            for (int mf = 0; mf < 2; mf++)
#pragma unroll
                for (int nf = 0; nf < 8; nf++) {
                    mma_tf32(acc[mf][nf], a_hi[mf], b_hi[nf]);
                    mma_tf32(acc[mf][nf], a_lo[mf], b_hi[nf]);
                    mma_tf32(acc[mf][nf], a_hi[mf], b_lo[nf]);
                }
        }
        __syncthreads();
    }

    // epilogue: fragment c0:(r,c) c1:(r,c+1) c2:(r+8,c) c3:(r+8,c+1)
#pragma unroll
    for (int mf = 0; mf < 2; mf++) {
        int rbase = m0 + wm + mf * 16 + gr;
#pragma unroll
        for (int nf = 0; nf < 8; nf++) {
            int cbase = n0 + wn + nf * 8 + gc * 2;
#pragma unroll
            for (int half = 0; half < 2; half++) {
                int m = rbase + half * 8;
                if (m >= M) continue;
#pragma unroll
                for (int jj = 0; jj < 2; jj++) {
                    int n = cbase + jj;
                    float val = acc[mf][nf][half * 2 + jj] + bias[n];
                    if (MODE == 0) {
                        C[((n >> 6) * SEQ + m) * 64 + (n & 63)] = val;
                    } else {
                        int r = (m >= T_TXT) ? (m - T_TXT) : (SVID + m);
                        long long idx = (long long)r * N + n;
                        if (idx < out_limit) C[idx] = val;
                    }
                }
            }
        }
    }
}

// ---------------- per-(head,pos) LayerNorm(HD=64) + RoPE on video rows ----------------
__global__ void __launch_bounds__(128) ln_rope_kernel(
    float* __restrict__ qbuf, float* __restrict__ kbuf,
    const float* __restrict__ cosb, const float* __restrict__ sinb,
    const float* __restrict__ nqw, const float* __restrict__ nqb,
    const float* __restrict__ nkw, const float* __restrict__ nkb)
{
    int warp = threadIdx.x >> 5, lane = threadIdx.x & 31;
    int row = blockIdx.x * 4 + warp;
    const int ROWS = NH * SEQ;
    if (row >= 2 * ROWS) return;
    int zk = (row >= ROWS) ? 1 : 0;
    int rem = zk ? (row - ROWS) : row;
    int s = rem % SEQ;
    float* x = (zk ? kbuf : qbuf) + rem * HD;
    const float* wgt = zk ? nkw : nqw;
    const float* bia = zk ? nkb : nqb;

    float v0 = x[2 * lane], v1 = x[2 * lane + 1];
    float sum = v0 + v1;
#pragma unroll
    for (int o = 16; o; o >>= 1) sum += __shfl_xor_sync(0xffffffffu, sum, o);
    float mu = sum * (1.f / 64.f);
    float d0 = v0 - mu, d1 = v1 - mu;
    float vs = d0 * d0 + d1 * d1;
#pragma unroll
    for (int o = 16; o; o >>= 1) vs += __shfl_xor_sync(0xffffffffu, vs, o);
    float rstd = rsqrtf(vs * (1.f / 64.f) + 1e-6f);
    float y0 = d0 * rstd * wgt[2 * lane] + bia[2 * lane];
    float y1 = d1 * rstd * wgt[2 * lane + 1] + bia[2 * lane + 1];
    if (s >= T_TXT) {
        int sv = s - T_TXT;
        float c0 = cosb[sv * HD + 2 * lane], c1 = cosb[sv * HD + 2 * lane + 1];
        float sn0 = sinb[sv * HD + 2 * lane], sn1 = sinb[sv * HD + 2 * lane + 1];
        float r0v = y0 * c0 - y1 * sn0;   // x_rot[2i]   = -x[2i+1]
        float r1v = y1 * c1 + y0 * sn1;   // x_rot[2i+1] =  x[2i]
        y0 = r0v; y1 = r1v;
    }
    x[2 * lane] = y0;
    x[2 * lane + 1] = y1;
}

// ---------------- flash attention, fp32, BQ=64 BKV=32 ----------------
__global__ void __launch_bounds__(256) attention_kernel(
    const float* __restrict__ q, const float* __restrict__ k,
    const float* __restrict__ v, float* __restrict__ attn)
{
    __shared__ __align__(16) float Qs[64][65];
    __shared__ __align__(16) float Ks[32][65];
    __shared__ __align__(16) float Vs[32][68];
    __shared__ __align__(16) float Ps[64][36];
    __shared__ float ms[64], ls[64], cs[64];

    int tid = threadIdx.x;
    int h = blockIdx.y;
    int q0 = blockIdx.x * 64;
    const float* qh = q + (h * SEQ) * HD;
    const float* kh = k + (h * SEQ) * HD;
    const float* vh = v + (h * SEQ) * HD;

#pragma unroll
    for (int i = 0; i < 16; i++) {
        int idx = tid + i * 256;
        int r = idx >> 6, d = idx & 63;
        Qs[r][d] = (q0 + r < SEQ) ? qh[(q0 + r) * HD + d] : 0.f;
    }
    if (tid < 64) { ms[tid] = -1e30f; ls[tid] = 0.f; }
    float O[4][4] = {};
    __syncthreads();

    int tr = tid >> 3, tc = tid & 7;
    int r0 = tr * 2, c0 = tc * 4;
    int ty = tid >> 4, tx = tid & 15;

    for (int kv0 = 0; kv0 < SEQ; kv0 += 32) {
        int jmax = min(32, SEQ - kv0);
        // load K/V tile
#pragma unroll
        for (int i = 0; i < 8; i++) {
            int idx = tid + i * 256;
            int r = idx >> 6, d = idx & 63;
            float kk = (r < jmax) ? kh[(kv0 + r) * HD + d] : 0.f;
            float vv = (r < jmax) ? vh[(kv0 + r) * HD + d] : 0.f;
            Ks[r][d] = kk;
            Vs[r][d] = vv;
        }
        __syncthreads();

        // scores: 2 q-rows x 4 k-cols per thread
        float s0[4] = {}, s1[4] = {};
#pragma unroll
        for (int d = 0; d < 64; d++) {
            float qa = Qs[r0][d], qb = Qs[r0 + 1][d];
            float k0v = Ks[c0][d], k1v = Ks[c0 + 1][d];
            float k2v = Ks[c0 + 2][d], k3v = Ks[c0 + 3][d];
            s0[0] += qa * k0v; s0[1] += qa * k1v; s0[2] += qa * k2v; s0[3] += qa * k3v;
            s1[0] += qb * k0v; s1[1] += qb * k1v; s1[2] += qb * k2v; s1[3] += qb * k3v;
        }
#pragma unroll
        for (int j = 0; j < 4; j++) {
            Ps[r0][c0 + j] = s0[j] * 0.125f;
            Ps[r0 + 1][c0 + j] = s1[j] * 0.125f;
        }
        __syncthreads();

        // online softmax stats (one thread per q-row)
        if (tid < 64) {
            float mo = ms[tid], mx = mo;
            for (int j = 0; j < jmax; j++) mx = fmaxf(mx, Ps[tid][j]);
            float c = __expf(mo - mx);
            float sum = 0.f;
            for (int j = 0; j < jmax; j++) {
                float p = __expf(Ps[tid][j] - mx);
                Ps[tid][j] = p;
                sum += p;
            }
            for (int j = jmax; j < 32; j++) Ps[tid][j] = 0.f;
            ls[tid] = ls[tid] * c + sum;
            ms[tid] = mx;
            cs[tid] = c;
        }
        __syncthreads();

        // O = O*c + P @ V   (4 q-rows x 4 d-cols per thread)
        float cc[4];
#pragma unroll
        for (int ii = 0; ii < 4; ii++) cc[ii] = cs[ty * 4 + ii];
#pragma unroll
        for (int ii = 0; ii < 4; ii++)
#pragma unroll
            for (int jj = 0; jj < 4; jj++) O[ii][jj] *= cc[ii];
#pragma unroll 4
        for (int j = 0; j < 32; j++) {
            float4 vv = *(const float4*)&Vs[j][tx * 4];
            float p0 = Ps[ty * 4 + 0][j];
            float p1 = Ps[ty * 4 + 1][j];
            float p2 = Ps[ty * 4 + 2][j];
            float p3 = Ps[ty * 4 + 3][j];
            O[0][0] += p0 * vv.x; O[0][1] += p0 * vv.y; O[0][2] += p0 * vv.z; O[0][3] += p0 * vv.w;
            O[1][0] += p1 * vv.x; O[1][1] += p1 * vv.y; O[1][2] += p1 * vv.z; O[1][3] += p1 * vv.w;
            O[2][0] += p2 * vv.x; O[2][1] += p2 * vv.y; O[2][2] += p2 * vv.z; O[2][3] += p2 * vv.w;
            O[3][0] += p3 * vv.x; O[3][1] += p3 * vv.y; O[3][2] += p3 * vv.z; O[3][3] += p3 * vv.w;
        }
        __syncthreads();
    }

#pragma unroll
    for (int ii = 0; ii < 4; ii++) {
        int s = q0 + ty * 4 + ii;
        if (s < SEQ) {
            float inv = 1.f / ls[ty * 4 + ii];
#pragma unroll
            for (int jj = 0; jj < 4; jj++)
                attn[s * DIMV + h * HD + tx * 4 + jj] = O[ii][jj] * inv;
        }
    }
}

// ---------------- conv1 (DIM->RANK, k=3, pad 1 over F=8) + exact GELU ----------------
__global__ void __launch_bounds__(128) conv1_gelu_kernel(
    const float* __restrict__ hidden, const float* __restrict__ w1,
    float* __restrict__ gel)
{
    __shared__ float xs[256][9];
    int p = blockIdx.x;       // spatial position 0..255
    int r = threadIdx.x;      // rank channel 0..127
    float acc[8] = {};
    for (int d0 = 0; d0 < DIMV; d0 += 256) {
        int dmax = min(256, DIMV - d0);
        for (int i = threadIdx.x; i < 2048; i += 128) {
            int d = i & 255, f = i >> 8;
            xs[d][f] = (d < dmax) ? hidden[(f * 256 + p) * DIMV + d0 + d] : 0.f;
        }
        __syncthreads();
#pragma unroll 2
        for (int d = 0; d < dmax; d++) {
            const float* w = w1 + r * (DIMV * 3) + (d0 + d) * 3;
            float w0 = w[0], wm = w[1], w2 = w[2];
            float xp[10];
            xp[0] = 0.f; xp[9] = 0.f;
#pragma unroll
            for (int f = 0; f < 8; f++) xp[f + 1] = xs[d][f];
#pragma unroll
            for (int f = 0; f < 8; f++)
                acc[f] += w0 * xp[f] + wm * xp[f + 1] + w2 * xp[f + 2];
        }
        __syncthreads();
    }
#pragma unroll
    for (int f = 0; f < 8; f++) {
        float x = acc[f];
        float g = 0.5f * x * (1.f + erff(x * 0.70710678118654752f));
        gel[(p * 128 + r) * 8 + f] = g;
    }
}

// ---------------- conv2 (RANK->DIM, k=3, pad 1) fused add into attn buffer ----------------
__global__ void __launch_bounds__(256) conv2_add_kernel(
    const float* __restrict__ w2, const float* __restrict__ gel,
    float* __restrict__ attn)
{
    __shared__ float gs[128][10];
    int p = blockIdx.x;
    int tid = threadIdx.x;
    for (int i = tid; i < 1024; i += 256) {
        int rr = i >> 3, f = i & 7;
        gs[rr][f + 1] = gel[(p * 128 + rr) * 8 + f];
    }
    if (tid < 128) { gs[tid][0] = 0.f; gs[tid][9] = 0.f; }
    __syncthreads();

    for (int d = tid; d < DIMV; d += 256) {
        float acc[8] = {};
        const float* w = w2 + d * 384;
#pragma unroll 2
        for (int rr = 0; rr < 128; rr++) {
            float w0 = w[rr * 3], wm = w[rr * 3 + 1], w2v = w[rr * 3 + 2];
#pragma unroll
            for (int f = 0; f < 8; f++)
                acc[f] += w0 * gs[rr][f] + wm * gs[rr][f + 1] + w2v * gs[rr][f + 2];
        }
#pragma unroll
        for (int f = 0; f < 8; f++) {
            int s = T_TXT + f * 256 + p;
            attn[s * DIMV + d] += acc[f];
        }
    }
}

// ---------------- launch ----------------
extern "C" void kernel_launch(void* const* d_in, const int* in_sizes, int n_in,
                              void* d_out, int out_size)
{
    const float* hidden = (const float*)d_in[0];
    const float* enc    = (const float*)d_in[1];
    const float* cosb   = (const float*)d_in[2];
    const float* sinb   = (const float*)d_in[3];
    const float* qw = (const float*)d_in[4];
    const float* qb = (const float*)d_in[5];
    const float* kw = (const float*)d_in[6];
    const float* kb = (const float*)d_in[7];
    const float* vw = (const float*)d_in[8];
    const float* vb = (const float*)d_in[9];
    const float* nqw = (const float*)d_in[10];
    const float* nqb = (const float*)d_in[11];
    const float* nkw = (const float*)d_in[12];
    const float* nkb = (const float*)d_in[13];
    const float* w1 = (const float*)d_in[14];
    const float* w2 = (const float*)d_in[15];
    const float* ow = (const float*)d_in[16];
    const float* ob = (const float*)d_in[17];

    float *hs, *q, *k, *v, *attn, *gel;
    cudaGetSymbolAddress((void**)&hs,   g_hs);
    cudaGetSymbolAddress((void**)&q,    g_q);
    cudaGetSymbolAddress((void**)&k,    g_k);
    cudaGetSymbolAddress((void**)&v,    g_v);
    cudaGetSymbolAddress((void**)&attn, g_attn);
    cudaGetSymbolAddress((void**)&gel,  g_gelu);

    // hs = concat([encoder, hidden]) along sequence
    cudaMemcpyAsync(hs, enc, (size_t)T_TXT * DIMV * sizeof(float),
                    cudaMemcpyDeviceToDevice, 0);
    cudaMemcpyAsync(hs + T_TXT * DIMV, hidden, (size_t)SVID * DIMV * sizeof(float),
                    cudaMemcpyDeviceToDevice, 0);

    dim3 gg((SEQ + 127) / 128, DIMV / 128);   // 18 x 15
    gemm_tf32<0><<<gg, 256>>>(hs, qw, qb, q, SEQ, DIMV, DIMV, 0);
    gemm_tf32<0><<<gg, 256>>>(hs, kw, kb, k, SEQ, DIMV, DIMV, 0);
    gemm_tf32<0><<<gg, 256>>>(hs, vw, vb, v, SEQ, DIMV, DIMV, 0);

    ln_rope_kernel<<<(2 * NH * SEQ + 3) / 4, 128>>>(q, k, cosb, sinb, nqw, nqb, nkw, nkb);

    attention_kernel<<<dim3((SEQ + 63) / 64, NH), 256>>>(q, k, v, attn);

    conv1_gelu_kernel<<<256, 128>>>(hidden, w1, gel);
    conv2_add_kernel<<<256, 256>>>(w2, gel, attn);

    gemm_tf32<1><<<gg, 256>>>(attn, ow, ob, (float*)d_out, SEQ, DIMV, DIMV,
                              (long long)out_size);
}

// round 6
// speedup vs baseline: 1.3420x; 1.0399x over previous
#include <cuda_runtime.h>
#include <math.h>
#include <stdint.h>

#define DIMV 1920
#define T_TXT 226
#define SVID 2048
#define SEQ 2274
#define NH 30
#define HD 64

// ---------------- scratch (device globals; no allocation allowed) ----------------
__device__ float g_hs[SEQ * DIMV];        // concat(encoder, hidden)
__device__ float g_q[NH * SEQ * HD];      // head-major
__device__ float g_k[NH * SEQ * HD];
__device__ float g_v[NH * SEQ * HD];
__device__ float g_attn[SEQ * DIMV];      // attention output [s][dim] (+conv branch)
__device__ float g_gelu[256 * 128 * 8];   // conv1+gelu intermediate [p][r][f]

// ---------------- tf32 helpers ----------------
__device__ __forceinline__ uint32_t f2tf32(float x) {
    uint32_t r;
    asm("cvt.rna.tf32.f32 %0, %1;" : "=r"(r) : "f"(x));
    return r;
}
__device__ __forceinline__ void split_tf32(float x, uint32_t& hi, uint32_t& lo) {
    hi = f2tf32(x);
    lo = f2tf32(x - __uint_as_float(hi));
}
__device__ __forceinline__ void mma_tf32(float* d, const uint32_t* a, const uint32_t* b) {
    asm volatile(
        "mma.sync.aligned.m16n8k8.row.col.f32.tf32.tf32.f32 "
        "{%0,%1,%2,%3}, {%4,%5,%6,%7}, {%8,%9}, {%0,%1,%2,%3};"
        : "+f"(d[0]), "+f"(d[1]), "+f"(d[2]), "+f"(d[3])
        : "r"(a[0]), "r"(a[1]), "r"(a[2]), "r"(a[3]), "r"(b[0]), "r"(b[1]));
}

// ---------------- 3xTF32 tensor-core NT GEMM: C = A(MxK) @ B(NxK)^T + bias ----------------
template <int MODE>
__global__ void __launch_bounds__(256) gemm_tf32(
    const float* __restrict__ A, const float* __restrict__ B,
    const float* __restrict__ bias, float* __restrict__ C,
    int M, int N, int K, long long out_limit)
{
    __shared__ __align__(16) float As[128][36];
    __shared__ __align__(16) float Bs[128][36];

    int tid  = threadIdx.x;
    int lane = tid & 31;
    int warp = tid >> 5;
    int wm = (warp >> 1) * 32;
    int wn = (warp & 1) * 64;
    int gr = lane >> 2;
    int gc = lane & 3;

    int m0 = blockIdx.x * 128, n0 = blockIdx.y * 128;

    float acc[2][8][4];
#pragma unroll
    for (int i = 0; i < 2; i++)
#pragma unroll
        for (int j = 0; j < 8; j++)
#pragma unroll
            for (int t = 0; t < 4; t++) acc[i][j][t] = 0.f;

    for (int k0 = 0; k0 < K; k0 += 32) {
#pragma unroll
        for (int i = 0; i < 4; i++) {
            int idx = tid + i * 256;
            int row = idx >> 3, c4 = idx & 7;
            float4 av = make_float4(0.f, 0.f, 0.f, 0.f);
            if (m0 + row < M)
                av = *(const float4*)&A[(size_t)(m0 + row) * K + k0 + c4 * 4];
            *(float4*)&As[row][c4 * 4] = av;
            float4 bv = *(const float4*)&B[(size_t)(n0 + row) * K + k0 + c4 * 4];
            *(float4*)&Bs[row][c4 * 4] = bv;
        }
        __syncthreads();

#pragma unroll
        for (int kk = 0; kk < 4; kk++) {
            int kb = kk * 8;
            uint32_t a_hi[2][4], a_lo[2][4];
#pragma unroll
            for (int mf = 0; mf < 2; mf++) {
                int r = wm + mf * 16 + gr;
                split_tf32(As[r][kb + gc],         a_hi[mf][0], a_lo[mf][0]);
                split_tf32(As[r + 8][kb + gc],     a_hi[mf][1], a_lo[mf][1]);
                split_tf32(As[r][kb + gc + 4],     a_hi[mf][2], a_lo[mf][2]);
                split_tf32(As[r + 8][kb + gc + 4], a_hi[mf][3], a_lo[mf][3]);
            }
            uint32_t b_hi[8][2], b_lo[8][2];
#pragma unroll
            for (int nf = 0; nf < 8; nf++) {
                int c = wn + nf * 8 + gr;
                split_tf32(Bs[c][kb + gc],     b_hi[nf][0], b_lo[nf][0]);
                split_tf32(Bs[c][kb + gc + 4], b_hi[nf][1], b_lo[nf][1]);
            }
#pragma unroll
            for (int mf = 0; mf < 2; mf++)
#pragma unroll
                for (int nf = 0; nf < 8; nf++) {
                    mma_tf32(acc[mf][nf], a_hi[mf], b_hi[nf]);
                    mma_tf32(acc[mf][nf], a_lo[mf], b_hi[nf]);
                    mma_tf32(acc[mf][nf], a_hi[mf], b_lo[nf]);
                }
        }
        __syncthreads();
    }

#pragma unroll
    for (int mf = 0; mf < 2; mf++) {
        int rbase = m0 + wm + mf * 16 + gr;
#pragma unroll
        for (int nf = 0; nf < 8; nf++) {
            int cbase = n0 + wn + nf * 8 + gc * 2;
#pragma unroll
            for (int half = 0; half < 2; half++) {
                int m = rbase + half * 8;
                if (m >= M) continue;
#pragma unroll
                for (int jj = 0; jj < 2; jj++) {
                    int n = cbase + jj;
                    float val = acc[mf][nf][half * 2 + jj] + bias[n];
                    if (MODE == 0) {
                        C[((n >> 6) * SEQ + m) * 64 + (n & 63)] = val;
                    } else {
                        int r = (m >= T_TXT) ? (m - T_TXT) : (SVID + m);
                        long long idx = (long long)r * N + n;
                        if (idx < out_limit) C[idx] = val;
                    }
                }
            }
        }
    }
}

// ---------------- per-(head,pos) LayerNorm(HD=64) + RoPE on video rows ----------------
__global__ void __launch_bounds__(128) ln_rope_kernel(
    float* __restrict__ qbuf, float* __restrict__ kbuf,
    const float* __restrict__ cosb, const float* __restrict__ sinb,
    const float* __restrict__ nqw, const float* __restrict__ nqb,
    const float* __restrict__ nkw, const float* __restrict__ nkb)
{
    int warp = threadIdx.x >> 5, lane = threadIdx.x & 31;
    int row = blockIdx.x * 4 + warp;
    const int ROWS = NH * SEQ;
    if (row >= 2 * ROWS) return;
    int zk = (row >= ROWS) ? 1 : 0;
    int rem = zk ? (row - ROWS) : row;
    int s = rem % SEQ;
    float* x = (zk ? kbuf : qbuf) + rem * HD;
    const float* wgt = zk ? nkw : nqw;
    const float* bia = zk ? nkb : nqb;

    float v0 = x[2 * lane], v1 = x[2 * lane + 1];
    float sum = v0 + v1;
#pragma unroll
    for (int o = 16; o; o >>= 1) sum += __shfl_xor_sync(0xffffffffu, sum, o);
    float mu = sum * (1.f / 64.f);
    float d0 = v0 - mu, d1 = v1 - mu;
    float vs = d0 * d0 + d1 * d1;
#pragma unroll
    for (int o = 16; o; o >>= 1) vs += __shfl_xor_sync(0xffffffffu, vs, o);
    float rstd = rsqrtf(vs * (1.f / 64.f) + 1e-6f);
    float y0 = d0 * rstd * wgt[2 * lane] + bia[2 * lane];
    float y1 = d1 * rstd * wgt[2 * lane + 1] + bia[2 * lane + 1];
    if (s >= T_TXT) {
        int sv = s - T_TXT;
        float c0 = cosb[sv * HD + 2 * lane], c1 = cosb[sv * HD + 2 * lane + 1];
        float sn0 = sinb[sv * HD + 2 * lane], sn1 = sinb[sv * HD + 2 * lane + 1];
        float r0v = y0 * c0 - y1 * sn0;
        float r1v = y1 * c1 + y0 * sn1;
        y0 = r0v; y1 = r1v;
    }
    x[2 * lane] = y0;
    x[2 * lane + 1] = y1;
}

// ---------------- flash attention, 3xTF32 tensor cores, BQ=64 BKV=32 ----------------
__global__ void __launch_bounds__(256) attention_mma_kernel(
    const float* __restrict__ q, const float* __restrict__ k,
    const float* __restrict__ v, float* __restrict__ attn)
{
    __shared__ __align__(16) float Qs[64][68];   // [q][d]
    __shared__ __align__(16) float Ks[32][68];   // [kv][d]
    __shared__ __align__(16) float Vs[64][36];   // [d][kv]  (transposed)
    __shared__ __align__(16) float Ps[64][36];   // [q][kv]  scores / probs
    __shared__ float ms[64], ls[64], cs[64];

    int tid  = threadIdx.x;
    int lane = tid & 31;
    int warp = tid >> 5;
    int gr = lane >> 2;          // 0..7
    int gc = lane & 3;           // 0..3
    int wm   = (warp >> 1) * 16; // q-row offset of warp (0,16,32,48)
    int wn16 = (warp & 1) * 16;  // kv-col offset for QK^T (0,16)
    int wn32 = (warp & 1) * 32;  // d-col offset for P@V (0,32)

    int h  = blockIdx.y;
    int q0 = blockIdx.x * 64;
    const float* qh = q + (size_t)(h * SEQ) * HD;
    const float* kh = k + (size_t)(h * SEQ) * HD;
    const float* vh = v + (size_t)(h * SEQ) * HD;

    // load Q tile (64x64), 4 threads per row, 4 float4 each
    {
        int r = tid >> 2, c16 = (tid & 3) * 16;
#pragma unroll
        for (int j = 0; j < 4; j++) {
            float4 val = make_float4(0.f, 0.f, 0.f, 0.f);
            if (q0 + r < SEQ)
                val = *(const float4*)&qh[(size_t)(q0 + r) * HD + c16 + j * 4];
            *(float4*)&Qs[r][c16 + j * 4] = val;
        }
    }
    if (tid < 64) { ms[tid] = -1e30f; ls[tid] = 0.f; }
    __syncthreads();

    // pre-split Q fragments (warp's m16 slice, all 8 k-steps) into registers
    uint32_t q_hi[8][4], q_lo[8][4];
#pragma unroll
    for (int ks = 0; ks < 8; ks++) {
        int kb = ks * 8;
        split_tf32(Qs[wm + gr][kb + gc],         q_hi[ks][0], q_lo[ks][0]);
        split_tf32(Qs[wm + gr + 8][kb + gc],     q_hi[ks][1], q_lo[ks][1]);
        split_tf32(Qs[wm + gr][kb + gc + 4],     q_hi[ks][2], q_lo[ks][2]);
        split_tf32(Qs[wm + gr + 8][kb + gc + 4], q_hi[ks][3], q_lo[ks][3]);
    }

    float oacc[4][4];
#pragma unroll
    for (int i = 0; i < 4; i++)
#pragma unroll
        for (int j = 0; j < 4; j++) oacc[i][j] = 0.f;

    for (int kv0 = 0; kv0 < SEQ; kv0 += 32) {
        int jmax = min(32, SEQ - kv0);

        // load K tile [kv][d]: 8 threads per row, 8 floats each
        {
            int r = tid >> 3, c8 = (tid & 7) * 8;
            float4 k0v = make_float4(0.f, 0.f, 0.f, 0.f);
            float4 k1v = make_float4(0.f, 0.f, 0.f, 0.f);
            if (r < jmax) {
                k0v = *(const float4*)&kh[(size_t)(kv0 + r) * HD + c8];
                k1v = *(const float4*)&kh[(size_t)(kv0 + r) * HD + c8 + 4];
            }
            *(float4*)&Ks[r][c8]     = k0v;
            *(float4*)&Ks[r][c8 + 4] = k1v;
        }
        // load V tile transposed -> Vs[d][kv]: lane = kv (conflict-free scatter)
        {
            int kvr = tid & 31, dbase = (tid >> 5) * 8;
            float4 v0 = make_float4(0.f, 0.f, 0.f, 0.f);
            float4 v1 = make_float4(0.f, 0.f, 0.f, 0.f);
            if (kvr < jmax) {
                v0 = *(const float4*)&vh[(size_t)(kv0 + kvr) * HD + dbase];
                v1 = *(const float4*)&vh[(size_t)(kv0 + kvr) * HD + dbase + 4];
            }
            Vs[dbase + 0][kvr] = v0.x; Vs[dbase + 1][kvr] = v0.y;
            Vs[dbase + 2][kvr] = v0.z; Vs[dbase + 3][kvr] = v0.w;
            Vs[dbase + 4][kvr] = v1.x; Vs[dbase + 5][kvr] = v1.y;
            Vs[dbase + 6][kvr] = v1.z; Vs[dbase + 7][kvr] = v1.w;
        }
        __syncthreads();

        // ---- S = Q @ K^T (3xTF32): warp tile m16 x n16, k=64 ----
        float sacc[2][4] = {};
#pragma unroll
        for (int ks = 0; ks < 8; ks++) {
            int kb = ks * 8;
#pragma unroll
            for (int nf = 0; nf < 2; nf++) {
                int n = wn16 + nf * 8 + gr;
                uint32_t bh[2], bl[2];
                split_tf32(Ks[n][kb + gc],     bh[0], bl[0]);
                split_tf32(Ks[n][kb + gc + 4], bh[1], bl[1]);
                mma_tf32(sacc[nf], q_hi[ks], bh);
                mma_tf32(sacc[nf], q_lo[ks], bh);
                mma_tf32(sacc[nf], q_hi[ks], bl);
            }
        }
        // store scaled scores to Ps
#pragma unroll
        for (int nf = 0; nf < 2; nf++) {
            int n2 = wn16 + nf * 8 + gc * 2;
            Ps[wm + gr][n2]         = sacc[nf][0] * 0.125f;
            Ps[wm + gr][n2 + 1]     = sacc[nf][1] * 0.125f;
            Ps[wm + gr + 8][n2]     = sacc[nf][2] * 0.125f;
            Ps[wm + gr + 8][n2 + 1] = sacc[nf][3] * 0.125f;
        }
        __syncthreads();

        // ---- online softmax: 4 threads per row, 8 entries each ----
        {
            int row = tid >> 2, qd = tid & 3;
            int jb = qd * 8;
            float mx = -1e30f;
#pragma unroll
            for (int j = 0; j < 8; j++)
                if (jb + j < jmax) mx = fmaxf(mx, Ps[row][jb + j]);
            mx = fmaxf(mx, __shfl_xor_sync(0xffffffffu, mx, 1));
            mx = fmaxf(mx, __shfl_xor_sync(0xffffffffu, mx, 2));
            float mo = ms[row];
            float mxn = fmaxf(mo, mx);
            float sum = 0.f;
#pragma unroll
            for (int j = 0; j < 8; j++) {
                float p = (jb + j < jmax) ? __expf(Ps[row][jb + j] - mxn) : 0.f;
                Ps[row][jb + j] = p;
                sum += p;
            }
            sum += __shfl_xor_sync(0xffffffffu, sum, 1);
            sum += __shfl_xor_sync(0xffffffffu, sum, 2);
            if (qd == 0) {
                float c = __expf(mo - mxn);
                ms[row] = mxn;
                ls[row] = ls[row] * c + sum;
                cs[row] = c;
            }
        }
        __syncthreads();

        // ---- O = O*c + P @ V (3xTF32): warp tile m16 x n32, k=32 ----
        {
            float c_lo = cs[wm + gr], c_hi = cs[wm + gr + 8];
#pragma unroll
            for (int nf = 0; nf < 4; nf++) {
                oacc[nf][0] *= c_lo; oacc[nf][1] *= c_lo;
                oacc[nf][2] *= c_hi; oacc[nf][3] *= c_hi;
            }
#pragma unroll
            for (int ks = 0; ks < 4; ks++) {
                int kb = ks * 8;
                uint32_t a_hi[4], a_lo[4];
                split_tf32(Ps[wm + gr][kb + gc],         a_hi[0], a_lo[0]);
                split_tf32(Ps[wm + gr + 8][kb + gc],     a_hi[1], a_lo[1]);
                split_tf32(Ps[wm + gr][kb + gc + 4],     a_hi[2], a_lo[2]);
                split_tf32(Ps[wm + gr + 8][kb + gc + 4], a_hi[3], a_lo[3]);
#pragma unroll
                for (int nf = 0; nf < 4; nf++) {
                    int n = wn32 + nf * 8 + gr;
                    uint32_t bh[2], bl[2];
                    split_tf32(Vs[n][kb + gc],     bh[0], bl[0]);
                    split_tf32(Vs[n][kb + gc + 4], bh[1], bl[1]);
                    mma_tf32(oacc[nf], a_hi, bh);
                    mma_tf32(oacc[nf], a_lo, bh);
                    mma_tf32(oacc[nf], a_hi, bl);
                }
            }
        }
        __syncthreads();
    }

    // ---- epilogue: O /= l, write to attn[s][h*64 + d] ----
    {
        float inv0 = 1.f / ls[wm + gr];
        float inv1 = 1.f / ls[wm + gr + 8];
        int s0 = q0 + wm + gr;
        int s1 = s0 + 8;
#pragma unroll
        for (int nf = 0; nf < 4; nf++) {
            int n2 = wn32 + nf * 8 + gc * 2;
            if (s0 < SEQ) {
                attn[(size_t)s0 * DIMV + h * HD + n2]     = oacc[nf][0] * inv0;
                attn[(size_t)s0 * DIMV + h * HD + n2 + 1] = oacc[nf][1] * inv0;
            }
            if (s1 < SEQ) {
                attn[(size_t)s1 * DIMV + h * HD + n2]     = oacc[nf][2] * inv1;
                attn[(size_t)s1 * DIMV + h * HD + n2 + 1] = oacc[nf][3] * inv1;
            }
        }
    }
}

// ---------------- conv1 (DIM->RANK, k=3, pad 1 over F=8) + exact GELU ----------------
__global__ void __launch_bounds__(128) conv1_gelu_kernel(
    const float* __restrict__ hidden, const float* __restrict__ w1,
    float* __restrict__ gel)
{
    __shared__ float xs[256][9];
    int p = blockIdx.x;
    int r = threadIdx.x;
    float acc[8] = {};
    for (int d0 = 0; d0 < DIMV; d0 += 256) {
        int dmax = min(256, DIMV - d0);
        for (int i = threadIdx.x; i < 2048; i += 128) {
            int d = i & 255, f = i >> 8;
            xs[d][f] = (d < dmax) ? hidden[(f * 256 + p) * DIMV + d0 + d] : 0.f;
        }
        __syncthreads();
#pragma unroll 2
        for (int d = 0; d < dmax; d++) {
            const float* w = w1 + r * (DIMV * 3) + (d0 + d) * 3;
            float w0 = w[0], wm = w[1], w2 = w[2];
            float xp[10];
            xp[0] = 0.f; xp[9] = 0.f;
#pragma unroll
            for (int f = 0; f < 8; f++) xp[f + 1] = xs[d][f];
#pragma unroll
            for (int f = 0; f < 8; f++)
                acc[f] += w0 * xp[f] + wm * xp[f + 1] + w2 * xp[f + 2];
        }
        __syncthreads();
    }
#pragma unroll
    for (int f = 0; f < 8; f++) {
        float x = acc[f];
        float g = 0.5f * x * (1.f + erff(x * 0.70710678118654752f));
        gel[(p * 128 + r) * 8 + f] = g;
    }
}

// ---------------- conv2 (RANK->DIM, k=3, pad 1) fused add into attn buffer ----------------
__global__ void __launch_bounds__(256) conv2_add_kernel(
    const float* __restrict__ w2, const float* __restrict__ gel,
    float* __restrict__ attn)
{
    __shared__ float gs[128][10];
    int p = blockIdx.x;
    int tid = threadIdx.x;
    for (int i = tid; i < 1024; i += 256) {
        int rr = i >> 3, f = i & 7;
        gs[rr][f + 1] = gel[(p * 128 + rr) * 8 + f];
    }
    if (tid < 128) { gs[tid][0] = 0.f; gs[tid][9] = 0.f; }
    __syncthreads();

    for (int d = tid; d < DIMV; d += 256) {
        float acc[8] = {};
        const float* w = w2 + d * 384;
#pragma unroll 2
        for (int rr = 0; rr < 128; rr++) {
            float w0 = w[rr * 3], wm = w[rr * 3 + 1], w2v = w[rr * 3 + 2];
#pragma unroll
            for (int f = 0; f < 8; f++)
                acc[f] += w0 * gs[rr][f] + wm * gs[rr][f + 1] + w2v * gs[rr][f + 2];
        }
#pragma unroll
        for (int f = 0; f < 8; f++) {
            int s = T_TXT + f * 256 + p;
            attn[s * DIMV + d] += acc[f];
        }
    }
}

// ---------------- launch ----------------
extern "C" void kernel_launch(void* const* d_in, const int* in_sizes, int n_in,
                              void* d_out, int out_size)
{
    const float* hidden = (const float*)d_in[0];
    const float* enc    = (const float*)d_in[1];
    const float* cosb   = (const float*)d_in[2];
    const float* sinb   = (const float*)d_in[3];
    const float* qw = (const float*)d_in[4];
    const float* qb = (const float*)d_in[5];
    const float* kw = (const float*)d_in[6];
    const float* kb = (const float*)d_in[7];
    const float* vw = (const float*)d_in[8];
    const float* vb = (const float*)d_in[9];
    const float* nqw = (const float*)d_in[10];
    const float* nqb = (const float*)d_in[11];
    const float* nkw = (const float*)d_in[12];
    const float* nkb = (const float*)d_in[13];
    const float* w1 = (const float*)d_in[14];
    const float* w2 = (const float*)d_in[15];
    const float* ow = (const float*)d_in[16];
    const float* ob = (const float*)d_in[17];

    float *hs, *q, *k, *v, *attn, *gel;
    cudaGetSymbolAddress((void**)&hs,   g_hs);
    cudaGetSymbolAddress((void**)&q,    g_q);
    cudaGetSymbolAddress((void**)&k,    g_k);
    cudaGetSymbolAddress((void**)&v,    g_v);
    cudaGetSymbolAddress((void**)&attn, g_attn);
    cudaGetSymbolAddress((void**)&gel,  g_gelu);

    cudaMemcpyAsync(hs, enc, (size_t)T_TXT * DIMV * sizeof(float),
                    cudaMemcpyDeviceToDevice, 0);
    cudaMemcpyAsync(hs + T_TXT * DIMV, hidden, (size_t)SVID * DIMV * sizeof(float),
                    cudaMemcpyDeviceToDevice, 0);

    dim3 gg((SEQ + 127) / 128, DIMV / 128);   // 18 x 15
    gemm_tf32<0><<<gg, 256>>>(hs, qw, qb, q, SEQ, DIMV, DIMV, 0);
    gemm_tf32<0><<<gg, 256>>>(hs, kw, kb, k, SEQ, DIMV, DIMV, 0);
    gemm_tf32<0><<<gg, 256>>>(hs, vw, vb, v, SEQ, DIMV, DIMV, 0);

    ln_rope_kernel<<<(2 * NH * SEQ + 3) / 4, 128>>>(q, k, cosb, sinb, nqw, nqb, nkw, nkb);

    attention_mma_kernel<<<dim3((SEQ + 63) / 64, NH), 256>>>(q, k, v, attn);

    conv1_gelu_kernel<<<256, 128>>>(hidden, w1, gel);
    conv2_add_kernel<<<256, 256>>>(w2, gel, attn);

    gemm_tf32<1><<<gg, 256>>>(attn, ow, ob, (float*)d_out, SEQ, DIMV, DIMV,
                              (long long)out_size);
}